// round 4
// baseline (speedup 1.0000x reference)
#include <cuda_runtime.h>
#include <stdint.h>

#define NUM_CLASSES 100000
#define EMBED_DIM   512
#define BATCH       16384

// -------------------------------------------------------------------------
// Kernel B: per-batch-row gather + loss + scatter-add.
//   block b handles batch row b. 128 threads, each owns 4 consecutive floats.
//   d = feature - center (pre-update center)
//   loss += d*d ;  out_center_row += 0.05 * d  (atomic, duplicates rare)
// -------------------------------------------------------------------------
__global__ __launch_bounds__(128)
void center_update_kernel(const float* __restrict__ features,
                          const int* __restrict__ labels,     // int32 (JAX x64 disabled)
                          const float* __restrict__ center_var,
                          float* __restrict__ out_centers,
                          float* __restrict__ loss_out) {
    const int b = blockIdx.x;
    const int t = threadIdx.x;

    const long long lbl = (long long)labels[b];

    const float4* frow = reinterpret_cast<const float4*>(features + (long long)b * EMBED_DIM);
    const float4* crow = reinterpret_cast<const float4*>(center_var + lbl * EMBED_DIM);
    float* orow = out_centers + lbl * EMBED_DIM;   // 4-byte aligned only; scalar atomics OK

    float4 f = frow[t];
    float4 c = crow[t];

    float dx = f.x - c.x;
    float dy = f.y - c.y;
    float dz = f.z - c.z;
    float dw = f.w - c.w;

    // scatter-add: update = -(1-ALPHA)*(c - f) = 0.05*(f - c)
    const float scale = 1.0f - 0.95f;
    atomicAdd(orow + 4 * t + 0, scale * dx);
    atomicAdd(orow + 4 * t + 1, scale * dy);
    atomicAdd(orow + 4 * t + 2, scale * dz);
    atomicAdd(orow + 4 * t + 3, scale * dw);

    // loss partial: sum of squared diffs
    float s = dx * dx + dy * dy + dz * dz + dw * dw;

    // warp reduce
    #pragma unroll
    for (int off = 16; off > 0; off >>= 1)
        s += __shfl_down_sync(0xFFFFFFFFu, s, off);

    __shared__ float warp_sums[4];
    if ((t & 31) == 0) warp_sums[t >> 5] = s;
    __syncthreads();

    if (t == 0) {
        float blk = warp_sums[0] + warp_sums[1] + warp_sums[2] + warp_sums[3];
        const float inv_n = 1.0f / ((float)BATCH * (float)EMBED_DIM);
        atomicAdd(loss_out, blk * inv_n);
    }
}

// -------------------------------------------------------------------------
// Launch
// -------------------------------------------------------------------------
extern "C" void kernel_launch(void* const* d_in, const int* in_sizes, int n_in,
                              void* d_out, int out_size) {
    const float* features   = (const float*)d_in[0];
    const int*   labels     = (const int*)d_in[1];
    const float* center_var = (const float*)d_in[2];

    float* out = (float*)d_out;
    float* loss_out    = out;       // out[0] = loss
    float* out_centers = out + 1;   // out[1:] = new_centers (4-byte aligned)

    // Zero the loss accumulator (4 bytes).
    cudaMemsetAsync(loss_out, 0, sizeof(float), 0);

    // Copy center_var -> out_centers. Driver memcpy handles the misaligned
    // (out+1) destination; D2D async memcpy is graph-capturable.
    cudaMemcpyAsync(out_centers, center_var,
                    (size_t)NUM_CLASSES * EMBED_DIM * sizeof(float),
                    cudaMemcpyDeviceToDevice, 0);

    // Kernel B: one block per batch row (same stream -> runs after the copy).
    center_update_kernel<<<BATCH, 128>>>(
        features, labels, center_var, out_centers, loss_out);
}

// round 5
// speedup vs baseline: 2.5646x; 2.5646x over previous
#include <cuda_runtime.h>
#include <stdint.h>

#define NUM_CLASSES 100000
#define EMBED_DIM   512
#define BATCH       16384
#define NUPD        BATCH      // one block per batch item (head blocks do the work)
#define NCOPY       6250       // copy blocks; each strides 16 rows

// Scratch: per-class linked list of batch items (duplicate-label grouping).
__device__ int g_head[NUM_CLASSES];
__device__ int g_next[BATCH];

// ---------------------------------------------------------------------------
// K0: reset head list + zero loss accumulator
// ---------------------------------------------------------------------------
__global__ void reset_kernel(float* __restrict__ loss_out) {
    int i = blockIdx.x * blockDim.x + threadIdx.x;
    if (i < NUM_CLASSES) g_head[i] = -1;
    if (i == 0) *loss_out = 0.0f;
}

// ---------------------------------------------------------------------------
// K1: build per-class chains: next[i] = old head, head[y_i] = i
// ---------------------------------------------------------------------------
__global__ void build_kernel(const int* __restrict__ labels) {
    int i = blockIdx.x * blockDim.x + threadIdx.x;
    if (i < BATCH) g_next[i] = atomicExch(&g_head[labels[i]], i);
}

// ---------------------------------------------------------------------------
// K2 (fused): blocks [0, NUPD) update touched rows (+ loss), blocks
// [NUPD, NUPD+NCOPY) stream-copy untouched rows. Writes are disjoint, so no
// ordering is needed between the two halves.
// ---------------------------------------------------------------------------
__global__ __launch_bounds__(128)
void fused_kernel(const float* __restrict__ features,
                  const int* __restrict__ labels,
                  const float* __restrict__ center_var,
                  float* __restrict__ out) {   // out[0]=loss, out+1=centers
    const int t = threadIdx.x;
    float* outc = out + 1;

    if (blockIdx.x < NUPD) {
        // ------------------ update path: one block per chain head ----------
        const int i = blockIdx.x;
        const int l = labels[i];
        if (g_head[l] != i) return;   // uniform per block; only head works

        const float4* crow =
            reinterpret_cast<const float4*>(center_var + (size_t)l * EMBED_DIM);
        float4 c = crow[t];

        float4 fs = make_float4(0.f, 0.f, 0.f, 0.f);
        float lossp = 0.f;
        int n = 0;

        // walk the duplicate chain (length 1 for ~98% of classes)
        for (int j = i; j >= 0; j = g_next[j]) {
            const float4* frow =
                reinterpret_cast<const float4*>(features + (size_t)j * EMBED_DIM);
            float4 f = frow[t];
            float dx = f.x - c.x, dy = f.y - c.y, dz = f.z - c.z, dw = f.w - c.w;
            lossp += dx * dx + dy * dy + dz * dz + dw * dw;
            fs.x += f.x; fs.y += f.y; fs.z += f.z; fs.w += f.w;
            n++;
        }

        // new = c + 0.05 * (sum_f - n*c)
        const float a = 0.05f;
        const float fn = (float)n;
        __shared__ float srow[EMBED_DIM];
        srow[4 * t + 0] = c.x + a * (fs.x - fn * c.x);
        srow[4 * t + 1] = c.y + a * (fs.y - fn * c.y);
        srow[4 * t + 2] = c.z + a * (fs.z - fn * c.z);
        srow[4 * t + 3] = c.w + a * (fs.w - fn * c.w);
        __syncthreads();

        // store with 16B-aligned pattern: dst row starts at (out+1)+512l,
        // so float offset 3 within the row is 16B-aligned.
        float* orow = outc + (size_t)l * EMBED_DIM;
        if (t < 127) {
            float4 v = make_float4(srow[4 * t + 3], srow[4 * t + 4],
                                   srow[4 * t + 5], srow[4 * t + 6]);
            *reinterpret_cast<float4*>(orow + 3 + 4 * t) = v;
        } else {
            orow[0] = srow[0]; orow[1] = srow[1]; orow[2] = srow[2];
            orow[511] = srow[511];
        }

        // block-reduce loss, single atomic per chain
        #pragma unroll
        for (int off = 16; off > 0; off >>= 1)
            lossp += __shfl_down_sync(0xFFFFFFFFu, lossp, off);
        __shared__ float ws[4];
        if ((t & 31) == 0) ws[t >> 5] = lossp;
        __syncthreads();
        if (t == 0) {
            const float inv_n = 1.0f / ((float)BATCH * (float)EMBED_DIM);
            atomicAdd(out, (ws[0] + ws[1] + ws[2] + ws[3]) * inv_n);
        }
    } else {
        // ------------------ copy path: untouched rows -----------------------
        const int cb = blockIdx.x - NUPD;
        for (int row = cb; row < NUM_CLASSES; row += NCOPY) {
            if (g_head[row] >= 0) continue;   // row owned by update path
            const float4* srcr =
                reinterpret_cast<const float4*>(center_var + (size_t)row * EMBED_DIM);
            float* dstr = outc + (size_t)row * EMBED_DIM;
            float4 a4 = srcr[t];
            if (t < 127) {
                float4 b4 = srcr[t + 1];   // L1-hit (neighbor lane's a4)
                *reinterpret_cast<float4*>(dstr + 3 + 4 * t) =
                    make_float4(a4.w, b4.x, b4.y, b4.z);
            } else {
                float4 h = srcr[0];
                dstr[0] = h.x; dstr[1] = h.y; dstr[2] = h.z;
                dstr[511] = a4.w;           // a4 = floats 508..511
            }
        }
    }
}

// ---------------------------------------------------------------------------
// Launch
// ---------------------------------------------------------------------------
extern "C" void kernel_launch(void* const* d_in, const int* in_sizes, int n_in,
                              void* d_out, int out_size) {
    const float* features   = (const float*)d_in[0];
    const int*   labels     = (const int*)d_in[1];
    const float* center_var = (const float*)d_in[2];
    float* out = (float*)d_out;

    reset_kernel<<<(NUM_CLASSES + 255) / 256, 256>>>(out);
    build_kernel<<<(BATCH + 255) / 256, 256>>>(labels);
    fused_kernel<<<NUPD + NCOPY, 128>>>(features, labels, center_var, out);
}

// round 6
// speedup vs baseline: 2.5821x; 1.0068x over previous
#include <cuda_runtime.h>
#include <stdint.h>

#define NUM_CLASSES 100000
#define EMBED_DIM   512
#define BATCH       16384
#define NUPD        BATCH      // one block per batch item (head blocks do the work)
#define NCOPY       6250       // copy blocks; each strides 16 rows

// Scratch: per-class linked list of batch items (duplicate-label grouping).
__device__ int g_head[NUM_CLASSES];
__device__ int g_next[BATCH];

// ---------------------------------------------------------------------------
// K0: reset head list + zero loss accumulator
// ---------------------------------------------------------------------------
__global__ void reset_kernel(float* __restrict__ loss_out) {
    int i = blockIdx.x * blockDim.x + threadIdx.x;
    if (i < NUM_CLASSES) g_head[i] = -1;
    if (i == 0) *loss_out = 0.0f;
}

// ---------------------------------------------------------------------------
// K1: build per-class chains: next[i] = old head, head[y_i] = i
// ---------------------------------------------------------------------------
__global__ void build_kernel(const int* __restrict__ labels) {
    int i = blockIdx.x * blockDim.x + threadIdx.x;
    if (i < BATCH) g_next[i] = atomicExch(&g_head[labels[i]], i);
}

// ---------------------------------------------------------------------------
// K2 (fused): blocks [0, NUPD) update touched rows (+ loss), blocks
// [NUPD, NUPD+NCOPY) stream-copy untouched rows. Writes are disjoint, so no
// ordering is needed between the two halves.
// ---------------------------------------------------------------------------
__global__ __launch_bounds__(128)
void fused_kernel(const float* __restrict__ features,
                  const int* __restrict__ labels,
                  const float* __restrict__ center_var,
                  float* __restrict__ out) {   // out[0]=loss, out+1=centers
    const int t = threadIdx.x;
    float* outc = out + 1;

    if (blockIdx.x < NUPD) {
        // ------------------ update path: one block per chain head ----------
        const int i = blockIdx.x;
        const int l = labels[i];
        if (g_head[l] != i) return;   // uniform per block; only head works

        const float4* crow =
            reinterpret_cast<const float4*>(center_var + (size_t)l * EMBED_DIM);
        float4 c = crow[t];

        float4 fs = make_float4(0.f, 0.f, 0.f, 0.f);
        float lossp = 0.f;
        int n = 0;

        // walk the duplicate chain (length 1 for ~98% of classes)
        for (int j = i; j >= 0; j = g_next[j]) {
            const float4* frow =
                reinterpret_cast<const float4*>(features + (size_t)j * EMBED_DIM);
            float4 f = frow[t];
            float dx = f.x - c.x, dy = f.y - c.y, dz = f.z - c.z, dw = f.w - c.w;
            lossp += dx * dx + dy * dy + dz * dz + dw * dw;
            fs.x += f.x; fs.y += f.y; fs.z += f.z; fs.w += f.w;
            n++;
        }

        // new = c + 0.05 * (sum_f - n*c)
        const float a = 0.05f;
        const float fn = (float)n;
        __shared__ float srow[EMBED_DIM];
        srow[4 * t + 0] = c.x + a * (fs.x - fn * c.x);
        srow[4 * t + 1] = c.y + a * (fs.y - fn * c.y);
        srow[4 * t + 2] = c.z + a * (fs.z - fn * c.z);
        srow[4 * t + 3] = c.w + a * (fs.w - fn * c.w);
        __syncthreads();

        // store with 16B-aligned pattern: dst row starts at (out+1)+512l,
        // so float offset 3 within the row is 16B-aligned.
        float* orow = outc + (size_t)l * EMBED_DIM;
        if (t < 127) {
            float4 v = make_float4(srow[4 * t + 3], srow[4 * t + 4],
                                   srow[4 * t + 5], srow[4 * t + 6]);
            *reinterpret_cast<float4*>(orow + 3 + 4 * t) = v;
        } else {
            orow[0] = srow[0]; orow[1] = srow[1]; orow[2] = srow[2];
            orow[511] = srow[511];
        }

        // block-reduce loss, single atomic per chain
        #pragma unroll
        for (int off = 16; off > 0; off >>= 1)
            lossp += __shfl_down_sync(0xFFFFFFFFu, lossp, off);
        __shared__ float ws[4];
        if ((t & 31) == 0) ws[t >> 5] = lossp;
        __syncthreads();
        if (t == 0) {
            const float inv_n = 1.0f / ((float)BATCH * (float)EMBED_DIM);
            atomicAdd(out, (ws[0] + ws[1] + ws[2] + ws[3]) * inv_n);
        }
    } else {
        // ------------------ copy path: untouched rows -----------------------
        const int cb = blockIdx.x - NUPD;
        for (int row = cb; row < NUM_CLASSES; row += NCOPY) {
            if (g_head[row] >= 0) continue;   // row owned by update path
            const float4* srcr =
                reinterpret_cast<const float4*>(center_var + (size_t)row * EMBED_DIM);
            float* dstr = outc + (size_t)row * EMBED_DIM;
            float4 a4 = srcr[t];
            if (t < 127) {
                float4 b4 = srcr[t + 1];   // L1-hit (neighbor lane's a4)
                *reinterpret_cast<float4*>(dstr + 3 + 4 * t) =
                    make_float4(a4.w, b4.x, b4.y, b4.z);
            } else {
                float4 h = srcr[0];
                dstr[0] = h.x; dstr[1] = h.y; dstr[2] = h.z;
                dstr[511] = a4.w;           // a4 = floats 508..511
            }
        }
    }
}

// ---------------------------------------------------------------------------
// Launch
// ---------------------------------------------------------------------------
extern "C" void kernel_launch(void* const* d_in, const int* in_sizes, int n_in,
                              void* d_out, int out_size) {
    const float* features   = (const float*)d_in[0];
    const int*   labels     = (const int*)d_in[1];
    const float* center_var = (const float*)d_in[2];
    float* out = (float*)d_out;

    reset_kernel<<<(NUM_CLASSES + 255) / 256, 256>>>(out);
    build_kernel<<<(BATCH + 255) / 256, 256>>>(labels);
    fused_kernel<<<NUPD + NCOPY, 128>>>(features, labels, center_var, out);
}